// round 16
// baseline (speedup 1.0000x reference)
#include <cuda_runtime.h>
#include <cuda_bf16.h>
#include <math_constants.h>
#include <cstdint>

// Problem shapes
#define NROWS 1024
#define DDIM  256
#define KCOLS 65536

// GEMM tiling: 128-thread CTAs, 4 warps (2M x 2N), warp tile 64x64
// Each CTA processes TWO adjacent col tiles via one flat 8-chunk pipeline.
#define BM 128
#define BN 128
#define DK 64
#define NCHUNKS (DDIM / DK)            // 4
#define NCOLBLK (KCOLS / BN)           // 512
#define NPART   NCOLBLK
#define THREADS 128
#define NSTAGE 3
#define TILES_PER_CTA 2
#define FTOT (TILES_PER_CTA * NCHUNKS) // 8

#define A_CHUNK 16384                  // 128 rows * 128 B
#define B_CHUNK 16384
#define STAGE_BYTES (A_CHUNK + B_CHUNK)
#define SM_TOTAL (NSTAGE * STAGE_BYTES)        // 98304

#define SMEM_SWZ128(off) ((off) ^ (((off) >> 3) & 0x70))
#define LOG2E 1.4426950408889634f
#define LN2   0.6931471805599453f

// Scratch (device globals: allocation-free)
__device__ __nv_bfloat16 gA[NROWS * DDIM];            // 0.5 MB row-major
__device__ __nv_bfloat16 gQt[(size_t)KCOLS * DDIM];   // 32 MB [n][k] K-major
__device__ float g_pm[NROWS * NPART];                 // base-2 max
__device__ float g_ps[NROWS * NPART];                 // base-2 sumexp
__device__ float g_loss[NROWS];

// ------------------------- helpers --------------------------
__device__ __forceinline__ uint32_t smem_u32(const void* p) {
    uint32_t a;
    asm("{ .reg .u64 t; cvta.to.shared.u64 t, %1; cvt.u32.u64 %0, t; }"
        : "=r"(a) : "l"(p));
    return a;
}
__device__ __forceinline__ void cp_async16(uint32_t s, const void* g) {
    asm volatile("cp.async.cg.shared.global [%0], [%1], 16;" :: "r"(s), "l"(g));
}
#define CP_COMMIT() asm volatile("cp.async.commit_group;" ::: "memory")
#define CP_WAIT1()  asm volatile("cp.async.wait_group 1;" ::: "memory")
#define CP_WAIT0()  asm volatile("cp.async.wait_group 0;" ::: "memory")

__device__ __forceinline__ void ldsm_x4(uint32_t& r0, uint32_t& r1,
                                        uint32_t& r2, uint32_t& r3, uint32_t a) {
    asm volatile("ldmatrix.sync.aligned.m8n8.x4.shared.b16 {%0,%1,%2,%3}, [%4];"
                 : "=r"(r0), "=r"(r1), "=r"(r2), "=r"(r3) : "r"(a));
}

// -------------------------------------------------------------------------
// Prep: online fp32 -> bf16
// -------------------------------------------------------------------------
__global__ void __launch_bounds__(256)
conv_a_kernel(const float* __restrict__ A)
{
    int i = blockIdx.x * blockDim.x + threadIdx.x;   // 65536 float4s
    float4 v = reinterpret_cast<const float4*>(A)[i];
    __nv_bfloat162* o = reinterpret_cast<__nv_bfloat162*>(gA) + i * 2;
    o[0] = __floats2bfloat162_rn(v.x, v.y);
    o[1] = __floats2bfloat162_rn(v.z, v.w);
}

// -------------------------------------------------------------------------
// Prep: queue fp32 [256 k][65536 n] -> Qt bf16 [65536 n][256 k]
// -------------------------------------------------------------------------
__global__ void __launch_bounds__(256)
transpose_q_kernel(const float* __restrict__ Q)
{
    __shared__ float tile[64][65];
    const int t  = threadIdx.x;
    const int nb = blockIdx.x * 64;
    const int kb = blockIdx.y * 64;

#pragma unroll
    for (int i = 0; i < 4; i++) {
        int row = (t >> 4) + i * 16;
        int c4  = (t & 15) * 4;
        float4 v = *reinterpret_cast<const float4*>(
            Q + (size_t)(kb + row) * KCOLS + nb + c4);
        tile[row][c4 + 0] = v.x;
        tile[row][c4 + 1] = v.y;
        tile[row][c4 + 2] = v.z;
        tile[row][c4 + 3] = v.w;
    }
    __syncthreads();

#pragma unroll
    for (int i = 0; i < 2; i++) {
        int n  = (t >> 3) + i * 32;
        int k8 = (t & 7) * 8;
        __nv_bfloat162 p[4];
#pragma unroll
        for (int j = 0; j < 4; j++)
            p[j] = __floats2bfloat162_rn(tile[k8 + 2 * j][n], tile[k8 + 2 * j + 1][n]);
        *reinterpret_cast<float4*>(gQt + (size_t)(nb + n) * DDIM + kb + k8) =
            *reinterpret_cast<float4*>(p);
    }
}

// -------------------------------------------------------------------------
// GEMM: 2 col tiles per CTA, flat 8-chunk 3-stage pipeline.
// Interior epilogue overlaps next tile's prefetch. Base-2 LSE.
// grid (256, 8), 128 threads, warp tile 64x64, 2 CTAs/SM
// -------------------------------------------------------------------------
__global__ void __launch_bounds__(THREADS, 2)
gemm_lse_kernel(const float* __restrict__ temp)
{
    extern __shared__ char smem[];
    __shared__ float red_m[2][BM];
    __shared__ float red_s[2][BM];

    const uint32_t sb = smem_u32(smem);
    const int tid   = threadIdx.x;
    const int lane  = tid & 31;
    const int warp  = tid >> 5;                   // 0..3
    const int warpM = warp >> 1;                  // 0..1 (64 rows)
    const int warpN = warp & 1;                   // 0..1 (64 cols)
    const int g     = lane >> 2;                  // 0..7
    const int t     = lane & 3;                   // 0..3

    const int rowBase = blockIdx.y * BM;
    const __nv_bfloat16* Arow = gA + (size_t)rowBase * DDIM;

    const int lrow = tid >> 3;                    // 0..15 (+i*16)
    const int lseg = tid & 7;                     // 16B segment

    float acc[4][8][4];
#pragma unroll
    for (int mi = 0; mi < 4; mi++)
#pragma unroll
        for (int ni = 0; ni < 8; ni++)
#pragma unroll
            for (int c = 0; c < 4; c++) acc[mi][ni][c] = 0.f;

    const int lq = lane >> 3;
    const int lr = lane & 7;
    const uint32_t aoffBase = (uint32_t)(((lq & 1) * 8 + lr) * 128 + (lq >> 1) * 16);
    const uint32_t boffBase = (uint32_t)(((lq >> 1) * 8 + lr) * 128 + (lq & 1) * 16);

    // scale in base-2 domain (one read; uniform)
    const float scale2 = (1.0f / temp[0]) * LOG2E;

    auto load_chunk = [&](int f) {
        const int kc   = f & (NCHUNKS - 1);
        const int colBlk = blockIdx.x * TILES_PER_CTA + (f >> 2);
        const __nv_bfloat16* Brow = gQt + (size_t)colBlk * BN * DDIM;
        const uint32_t abase = sb + (f % NSTAGE) * STAGE_BYTES;
        const uint32_t bbase = abase + A_CHUNK;
#pragma unroll
        for (int i = 0; i < 8; i++) {
            int row = lrow + i * 16;
            uint32_t off = SMEM_SWZ128((uint32_t)(row * 128 + lseg * 16));
            cp_async16(abase + off, Arow + (size_t)row * DDIM + kc * DK + lseg * 8);
        }
#pragma unroll
        for (int i = 0; i < 8; i++) {
            int row = lrow + i * 16;
            uint32_t off = SMEM_SWZ128((uint32_t)(row * 128 + lseg * 16));
            cp_async16(bbase + off, Brow + (size_t)row * DDIM + kc * DK + lseg * 8);
        }
    };

    // fragment buffers (double)
    unsigned afr[2][4][4];
    unsigned bfr[2][8][2];
    auto load_frags = [&](uint32_t abase, uint32_t bbase, int kk, int buf) {
        const uint32_t kbyte = (uint32_t)(kk * 32);
#pragma unroll
        for (int mi = 0; mi < 4; mi++) {
            int ra = warpM * 64 + mi * 16;
            uint32_t addr = abase +
                SMEM_SWZ128((uint32_t)(ra * 128) + aoffBase + kbyte);
            ldsm_x4(afr[buf][mi][0], afr[buf][mi][1],
                    afr[buf][mi][2], afr[buf][mi][3], addr);
        }
#pragma unroll
        for (int np = 0; np < 4; np++) {
            int nb = warpN * 64 + np * 16;
            uint32_t addr = bbase +
                SMEM_SWZ128((uint32_t)(nb * 128) + boffBase + kbyte);
            ldsm_x4(bfr[buf][2 * np][0], bfr[buf][2 * np][1],
                    bfr[buf][2 * np + 1][0], bfr[buf][2 * np + 1][1], addr);
        }
    };

    // Epilogue for one finished tile (base-2 streaming LSE)
    auto tile_epilogue = [&](int colBlk) {
#pragma unroll
        for (int mi = 0; mi < 4; mi++) {
#pragma unroll
            for (int half = 0; half < 2; half++) {
                float v[16];
#pragma unroll
                for (int ni = 0; ni < 8; ni++) {
                    v[ni * 2 + 0] = acc[mi][ni][half * 2 + 0] * scale2;
                    v[ni * 2 + 1] = acc[mi][ni][half * 2 + 1] * scale2;
                }
                float m = v[0];
#pragma unroll
                for (int i = 1; i < 16; i++) m = fmaxf(m, v[i]);
                float s = 0.f;
#pragma unroll
                for (int i = 0; i < 16; i++) s += exp2f(v[i] - m);
#pragma unroll
                for (int off = 1; off <= 2; off <<= 1) {
                    float om = __shfl_xor_sync(0xffffffffu, m, off);
                    float os = __shfl_xor_sync(0xffffffffu, s, off);
                    float M = fmaxf(m, om);
                    s = s * exp2f(m - M) + os * exp2f(om - M);
                    m = M;
                }
                if (t == 0) {
                    int r = warpM * 64 + mi * 16 + half * 8 + g;
                    red_m[warpN][r] = m;
                    red_s[warpN][r] = s;
                }
            }
        }
        __syncthreads();
        if (tid < BM) {
            float m0 = red_m[0][tid], s0 = red_s[0][tid];
            float m1 = red_m[1][tid], s1 = red_s[1][tid];
            float M = fmaxf(m0, m1);
            float S = s0 * exp2f(m0 - M) + s1 * exp2f(m1 - M);
            int row = rowBase + tid;
            g_pm[(size_t)row * NPART + colBlk] = M;
            g_ps[(size_t)row * NPART + colBlk] = S;
        }
        // reset accumulators
#pragma unroll
        for (int mi = 0; mi < 4; mi++)
#pragma unroll
            for (int ni = 0; ni < 8; ni++)
#pragma unroll
                for (int c = 0; c < 4; c++) acc[mi][ni][c] = 0.f;
    };

    load_chunk(0); CP_COMMIT();
    load_chunk(1); CP_COMMIT();

#pragma unroll 1
    for (int f = 0; f < FTOT; f++) {
        if (f < FTOT - 1) { CP_WAIT1(); } else { CP_WAIT0(); }
        __syncthreads();

        if (f + 2 < FTOT) { load_chunk(f + 2); CP_COMMIT(); }

        const uint32_t abase = sb + (f % NSTAGE) * STAGE_BYTES;
        const uint32_t bbase = abase + A_CHUNK;

        load_frags(abase, bbase, 0, 0);
#pragma unroll
        for (int kk = 0; kk < DK / 16; kk++) {
            const int cur = kk & 1;
            if (kk + 1 < DK / 16) load_frags(abase, bbase, kk + 1, cur ^ 1);
#pragma unroll
            for (int mi = 0; mi < 4; mi++)
#pragma unroll
                for (int ni = 0; ni < 8; ni++) {
                    asm volatile(
                        "mma.sync.aligned.m16n8k16.row.col.f32.bf16.bf16.f32 "
                        "{%0,%1,%2,%3}, {%4,%5,%6,%7}, {%8,%9}, {%0,%1,%2,%3};"
                        : "+f"(acc[mi][ni][0]), "+f"(acc[mi][ni][1]),
                          "+f"(acc[mi][ni][2]), "+f"(acc[mi][ni][3])
                        : "r"(afr[cur][mi][0]), "r"(afr[cur][mi][1]),
                          "r"(afr[cur][mi][2]), "r"(afr[cur][mi][3]),
                          "r"(bfr[cur][ni][0]), "r"(bfr[cur][ni][1]));
                }
        }

        // Tile boundary: epilogue overlaps the already-in-flight prefetch
        // of the next tile's first two chunks.
        if ((f & (NCHUNKS - 1)) == NCHUNKS - 1)
            tile_epilogue(blockIdx.x * TILES_PER_CTA + (f >> 2));
    }
}

// -------------------------------------------------------------------------
__device__ inline void lse_comb2(float& m, float& s, float m2, float s2)
{
    float M = fmaxf(m, m2);
    s = s * exp2f(m - M) + s2 * exp2f(m2 - M);
    m = M;
}

// Per-row combine (base-2), vectorized
__global__ void __launch_bounds__(128)
row_reduce_kernel(const float* __restrict__ online,
                  const float* __restrict__ mom,
                  const float* __restrict__ temp)
{
    const int row = blockIdx.x;
    const int tid = threadIdx.x;
    __shared__ float sm[128], ss[128], sp[128];

    float4 m4 = reinterpret_cast<const float4*>(g_pm + (size_t)row * NPART)[tid];
    float4 s4 = reinterpret_cast<const float4*>(g_ps + (size_t)row * NPART)[tid];
    float m = m4.x, s = s4.x;
    lse_comb2(m, s, m4.y, s4.y);
    lse_comb2(m, s, m4.z, s4.z);
    lse_comb2(m, s, m4.w, s4.w);

    float2 o  = reinterpret_cast<const float2*>(online + (size_t)row * DDIM)[tid];
    float2 mo = reinterpret_cast<const float2*>(mom    + (size_t)row * DDIM)[tid];
    float pv = o.x * mo.x + o.y * mo.y;

    sm[tid] = m; ss[tid] = s; sp[tid] = pv;
    __syncthreads();
    for (int o2 = 64; o2 > 0; o2 >>= 1) {
        if (tid < o2) {
            float mm = sm[tid], sv = ss[tid];
            lse_comb2(mm, sv, sm[tid + o2], ss[tid + o2]);
            sm[tid] = mm; ss[tid] = sv;
            sp[tid] += sp[tid + o2];
        }
        __syncthreads();
    }
    if (tid == 0) {
        float scale2 = (1.0f / temp[0]) * LOG2E;
        float pos2 = sp[0] * scale2;              // positive logit, base-2 domain
        float M = fmaxf(sm[0], pos2);
        float S = ss[0] * exp2f(sm[0] - M) + exp2f(pos2 - M);
        g_loss[row] = LN2 * (M + log2f(S) - pos2);
    }
}

__global__ void __launch_bounds__(256)
final_mean_kernel(float* __restrict__ out)
{
    const int tid = threadIdx.x;
    __shared__ float sb[256];
    sb[tid] = g_loss[tid] + g_loss[tid + 256] + g_loss[tid + 512] + g_loss[tid + 768];
    __syncthreads();
    for (int o = 128; o > 0; o >>= 1) {
        if (tid < o) sb[tid] += sb[tid + o];
        __syncthreads();
    }
    if (tid == 0) {
        float l = sb[0] * (1.0f / (float)NROWS);
        out[0] = 0.7f * l + 0.3f * l;
    }
}

// -------------------------------------------------------------------------
extern "C" void kernel_launch(void* const* d_in, const int* in_sizes, int n_in,
                              void* d_out, int out_size)
{
    const float* online = (const float*)d_in[0];   // [1024, 256]
    const float* mom    = (const float*)d_in[1];   // [1024, 256]
    const float* queue  = (const float*)d_in[2];   // [256, 65536]
    const float* temp   = (const float*)d_in[3];   // [1]
    float* out = (float*)d_out;

    cudaFuncSetAttribute(gemm_lse_kernel,
                         cudaFuncAttributeMaxDynamicSharedMemorySize, SM_TOTAL);

    conv_a_kernel<<<256, 256>>>(online);
    {
        dim3 g(KCOLS / 64, DDIM / 64);             // (1024, 4)
        transpose_q_kernel<<<g, 256>>>(queue);
    }
    {
        dim3 g(NCOLBLK / TILES_PER_CTA, NROWS / BM);   // (256, 8)
        gemm_lse_kernel<<<g, THREADS, SM_TOTAL>>>(temp);
    }
    row_reduce_kernel<<<NROWS, 128>>>(online, mom, temp);
    final_mean_kernel<<<1, 256>>>(out);
}

// round 17
// speedup vs baseline: 1.0506x; 1.0506x over previous
#include <cuda_runtime.h>
#include <cuda_bf16.h>
#include <math_constants.h>
#include <cstdint>

// Problem shapes
#define NROWS 1024
#define DDIM  256
#define KCOLS 65536

// GEMM tiling: 128-thread CTAs, 4 warps (2M x 2N), warp tile 64x64
// Two adjacent col tiles per CTA, flat 8-chunk pipeline, bulk-copy loads.
#define BM 128
#define BN 128
#define DK 64
#define NCHUNKS (DDIM / DK)            // 4
#define NCOLBLK (KCOLS / BN)           // 512
#define NROWBLK (NROWS / BM)           // 8
#define NPART   NCOLBLK
#define THREADS 128
#define NSTAGE 3
#define TILES_PER_CTA 2
#define FTOT (TILES_PER_CTA * NCHUNKS) // 8

#define CHUNK_BYTES 16384              // 128 rows x 128 B (swizzled)
#define STAGE_BYTES (2 * CHUNK_BYTES)  // A + B
#define SM_DATA 1024                   // stages start here (mbarriers below)
#define SM_TOTAL (SM_DATA + NSTAGE * STAGE_BYTES)   // 99328

#define SMEM_SWZ128(off) ((off) ^ (((off) >> 3) & 0x70))
#define LOG2E 1.4426950408889634f
#define LN2   0.6931471805599453f

// Scratch (device globals: allocation-free)
// Chunk-tiled, pre-swizzled bf16 layouts:
//   gA2[rowBlk][kc][16KB swizzled chunk], gQt2[colBlk][kc][16KB swizzled chunk]
__device__ __nv_bfloat16 gA2[NROWBLK * NCHUNKS * (CHUNK_BYTES / 2)];
__device__ __nv_bfloat16 gQt2[(size_t)NCOLBLK * NCHUNKS * (CHUNK_BYTES / 2)];
__device__ float g_pm[NROWS * NPART];                 // base-2 max
__device__ float g_ps[NROWS * NPART];                 // base-2 sumexp
__device__ float g_loss[NROWS];

// ------------------------- helpers --------------------------
__device__ __forceinline__ uint32_t smem_u32(const void* p) {
    uint32_t a;
    asm("{ .reg .u64 t; cvta.to.shared.u64 t, %1; cvt.u32.u64 %0, t; }"
        : "=r"(a) : "l"(p));
    return a;
}
__device__ __forceinline__ void ldsm_x4(uint32_t& r0, uint32_t& r1,
                                        uint32_t& r2, uint32_t& r3, uint32_t a) {
    asm volatile("ldmatrix.sync.aligned.m8n8.x4.shared.b16 {%0,%1,%2,%3}, [%4];"
                 : "=r"(r0), "=r"(r1), "=r"(r2), "=r"(r3) : "r"(a));
}
#define MBAR_INIT(mb, c) \
    asm volatile("mbarrier.init.shared.b64 [%0], %1;" \
                 :: "r"((uint32_t)(mb)), "r"((uint32_t)(c)) : "memory")
#define MBAR_EXPECT_TX(mb, bytes) \
    asm volatile("mbarrier.arrive.expect_tx.shared.b64 _, [%0], %1;" \
                 :: "r"((uint32_t)(mb)), "r"((uint32_t)(bytes)) : "memory")
#define MBAR_WAIT(mb, ph) do {                                               \
    uint32_t _m = (uint32_t)(mb), _p = (uint32_t)(ph), _d;                   \
    asm volatile("{\n\t.reg .pred p;\n\t"                                    \
        "mbarrier.try_wait.parity.shared.b64 p, [%1], %2;\n\t"               \
        "selp.b32 %0, 1, 0, p;\n\t}" : "=r"(_d) : "r"(_m), "r"(_p) : "memory"); \
    while (!_d) {                                                            \
        asm volatile("{\n\t.reg .pred p;\n\t"                                \
            "mbarrier.try_wait.parity.shared.b64 p, [%1], %2;\n\t"           \
            "selp.b32 %0, 1, 0, p;\n\t}" : "=r"(_d) : "r"(_m), "r"(_p) : "memory"); \
    }                                                                        \
} while (0)
__device__ __forceinline__ void bulk_ld(uint32_t dst, const void* src,
                                        uint32_t bytes, uint32_t mbar) {
    uint64_t g = (uint64_t)__cvta_generic_to_global(src);
    asm volatile(
        "cp.async.bulk.shared::cluster.global.mbarrier::complete_tx::bytes "
        "[%0], [%1], %2, [%3];"
        :: "r"(dst), "l"(g), "r"(bytes), "r"(mbar) : "memory");
}

// -------------------------------------------------------------------------
// Prep: online fp32 -> bf16, chunk-tiled + pre-swizzled
// 32768 16B-units: u -> chunk u/1024, row (u%1024)/8, seg u%8
// -------------------------------------------------------------------------
__global__ void __launch_bounds__(256)
conv_a_kernel(const float* __restrict__ A)
{
    int u = blockIdx.x * blockDim.x + threadIdx.x;   // 0..32767
    int chunk = u >> 10;                              // rowBlk*4 + kc
    int w     = u & 1023;
    int row   = w >> 3;                               // 0..127
    int seg   = w & 7;                                // 0..7
    int rowBlk = chunk >> 2;
    int kc     = chunk & 3;
    int gr = rowBlk * BM + row;
    int gk = kc * DK + seg * 8;

    const float4* src = reinterpret_cast<const float4*>(A + (size_t)gr * DDIM + gk);
    float4 v0 = src[0];
    float4 v1 = src[1];
    __nv_bfloat162 p[4];
    p[0] = __floats2bfloat162_rn(v0.x, v0.y);
    p[1] = __floats2bfloat162_rn(v0.z, v0.w);
    p[2] = __floats2bfloat162_rn(v1.x, v1.y);
    p[3] = __floats2bfloat162_rn(v1.z, v1.w);
    uint32_t off = SMEM_SWZ128((uint32_t)(row * 128 + seg * 16));
    *reinterpret_cast<float4*>(
        reinterpret_cast<char*>(gA2) + (size_t)chunk * CHUNK_BYTES + off) =
        *reinterpret_cast<float4*>(p);
}

// -------------------------------------------------------------------------
// Prep: queue fp32 [256 k][65536 n] -> gQt2 chunk-tiled pre-swizzled bf16
// -------------------------------------------------------------------------
__global__ void __launch_bounds__(256)
transpose_q_kernel(const float* __restrict__ Q)
{
    __shared__ float tile[64][65];
    const int t  = threadIdx.x;
    const int nb = blockIdx.x * 64;
    const int kb = blockIdx.y * 64;

#pragma unroll
    for (int i = 0; i < 4; i++) {
        int row = (t >> 4) + i * 16;                  // k within tile
        int c4  = (t & 15) * 4;                       // n within tile
        float4 v = *reinterpret_cast<const float4*>(
            Q + (size_t)(kb + row) * KCOLS + nb + c4);
        tile[row][c4 + 0] = v.x;
        tile[row][c4 + 1] = v.y;
        tile[row][c4 + 2] = v.z;
        tile[row][c4 + 3] = v.w;
    }
    __syncthreads();

    const int kc = kb >> 6;                           // global k chunk
#pragma unroll
    for (int i = 0; i < 2; i++) {
        int nl = (t >> 3) + i * 32;                   // n within tile
        int k8 = (t & 7) * 8;                         // k segment (local)
        __nv_bfloat162 p[4];
#pragma unroll
        for (int j = 0; j < 4; j++)
            p[j] = __floats2bfloat162_rn(tile[k8 + 2 * j][nl], tile[k8 + 2 * j + 1][nl]);
        int gn = nb + nl;
        int colBlk = gn >> 7;                         // /128
        int nrow   = gn & 127;
        uint32_t off = SMEM_SWZ128((uint32_t)(nrow * 128 + (t & 7) * 16));
        *reinterpret_cast<float4*>(
            reinterpret_cast<char*>(gQt2) +
            ((size_t)colBlk * NCHUNKS + kc) * CHUNK_BYTES + off) =
            *reinterpret_cast<float4*>(p);
    }
}

// -------------------------------------------------------------------------
// GEMM: bulk-copy (UBLKCP) loads, mbarrier pipeline, 2 col tiles per CTA.
// grid (256, 8), 128 threads, warp tile 64x64, 2 CTAs/SM
// -------------------------------------------------------------------------
__global__ void __launch_bounds__(THREADS, 2)
gemm_lse_kernel(const float* __restrict__ temp)
{
    extern __shared__ char smem[];
    __shared__ float red_m[2][BM];
    __shared__ float red_s[2][BM];

    const uint32_t sb = smem_u32(smem);
    const int tid   = threadIdx.x;
    const int lane  = tid & 31;
    const int warp  = tid >> 5;                   // 0..3
    const int warpM = warp >> 1;                  // 0..1 (64 rows)
    const int warpN = warp & 1;                   // 0..1 (64 cols)
    const int g     = lane >> 2;                  // 0..7
    const int t     = lane & 3;                   // 0..3

    const int rowBase = blockIdx.y * BM;

    float acc[4][8][4];
#pragma unroll
    for (int mi = 0; mi < 4; mi++)
#pragma unroll
        for (int ni = 0; ni < 8; ni++)
#pragma unroll
            for (int c = 0; c < 4; c++) acc[mi][ni][c] = 0.f;

    const int lq = lane >> 3;
    const int lr = lane & 7;
    const uint32_t aoffBase = (uint32_t)(((lq & 1) * 8 + lr) * 128 + (lq >> 1) * 16);
    const uint32_t boffBase = (uint32_t)(((lq >> 1) * 8 + lr) * 128 + (lq & 1) * 16);

    const float scale2 = (1.0f / temp[0]) * LOG2E;

    // mbarriers at sb + 8*s, stage data at sb + SM_DATA + s*STAGE_BYTES
    if (tid == 0) {
        MBAR_INIT(sb + 0, 1);
        MBAR_INIT(sb + 8, 1);
        MBAR_INIT(sb + 16, 1);
    }
    __syncthreads();

    auto issue_chunk = [&](int f) {
        const int kc = f & (NCHUNKS - 1);
        const int colBlk = blockIdx.x * TILES_PER_CTA + (f >> 2);
        const int s = f % NSTAGE;
        const uint32_t bar = sb + 8 * s;
        const uint32_t dst = sb + SM_DATA + s * STAGE_BYTES;
        MBAR_EXPECT_TX(bar, STAGE_BYTES);
        bulk_ld(dst,
                reinterpret_cast<const char*>(gA2) +
                    ((size_t)blockIdx.y * NCHUNKS + kc) * CHUNK_BYTES,
                CHUNK_BYTES, bar);
        bulk_ld(dst + CHUNK_BYTES,
                reinterpret_cast<const char*>(gQt2) +
                    ((size_t)colBlk * NCHUNKS + kc) * CHUNK_BYTES,
                CHUNK_BYTES, bar);
    };

    if (tid == 0) { issue_chunk(0); issue_chunk(1); }

    // fragment buffers (double)
    unsigned afr[2][4][4];
    unsigned bfr[2][8][2];
    auto load_frags = [&](uint32_t abase, uint32_t bbase, int kk, int buf) {
        const uint32_t kbyte = (uint32_t)(kk * 32);
#pragma unroll
        for (int mi = 0; mi < 4; mi++) {
            int ra = warpM * 64 + mi * 16;
            uint32_t addr = abase +
                SMEM_SWZ128((uint32_t)(ra * 128) + aoffBase + kbyte);
            ldsm_x4(afr[buf][mi][0], afr[buf][mi][1],
                    afr[buf][mi][2], afr[buf][mi][3], addr);
        }
#pragma unroll
        for (int np = 0; np < 4; np++) {
            int nb = warpN * 64 + np * 16;
            uint32_t addr = bbase +
                SMEM_SWZ128((uint32_t)(nb * 128) + boffBase + kbyte);
            ldsm_x4(bfr[buf][2 * np][0], bfr[buf][2 * np][1],
                    bfr[buf][2 * np + 1][0], bfr[buf][2 * np + 1][1], addr);
        }
    };

    auto tile_epilogue = [&](int colBlk) {
#pragma unroll
        for (int mi = 0; mi < 4; mi++) {
#pragma unroll
            for (int half = 0; half < 2; half++) {
                float v[16];
#pragma unroll
                for (int ni = 0; ni < 8; ni++) {
                    v[ni * 2 + 0] = acc[mi][ni][half * 2 + 0] * scale2;
                    v[ni * 2 + 1] = acc[mi][ni][half * 2 + 1] * scale2;
                }
                float m = v[0];
#pragma unroll
                for (int i = 1; i < 16; i++) m = fmaxf(m, v[i]);
                float s = 0.f;
#pragma unroll
                for (int i = 0; i < 16; i++) s += exp2f(v[i] - m);
#pragma unroll
                for (int off = 1; off <= 2; off <<= 1) {
                    float om = __shfl_xor_sync(0xffffffffu, m, off);
                    float os = __shfl_xor_sync(0xffffffffu, s, off);
                    float M = fmaxf(m, om);
                    s = s * exp2f(m - M) + os * exp2f(om - M);
                    m = M;
                }
                if (t == 0) {
                    int r = warpM * 64 + mi * 16 + half * 8 + g;
                    red_m[warpN][r] = m;
                    red_s[warpN][r] = s;
                }
            }
        }
        __syncthreads();
        if (tid < BM) {
            float m0 = red_m[0][tid], s0 = red_s[0][tid];
            float m1 = red_m[1][tid], s1 = red_s[1][tid];
            float M = fmaxf(m0, m1);
            float S = s0 * exp2f(m0 - M) + s1 * exp2f(m1 - M);
            int row = rowBase + tid;
            g_pm[(size_t)row * NPART + colBlk] = M;
            g_ps[(size_t)row * NPART + colBlk] = S;
        }
#pragma unroll
        for (int mi = 0; mi < 4; mi++)
#pragma unroll
            for (int ni = 0; ni < 8; ni++)
#pragma unroll
                for (int c = 0; c < 4; c++) acc[mi][ni][c] = 0.f;
    };

#pragma unroll 1
    for (int f = 0; f < FTOT; f++) {
        const int s = f % NSTAGE;
        MBAR_WAIT(sb + 8 * s, (f / NSTAGE) & 1);
        __syncthreads();   // all warps past prev compute; freed stage reusable

        if (tid == 0 && f + 2 < FTOT) issue_chunk(f + 2);

        const uint32_t abase = sb + SM_DATA + s * STAGE_BYTES;
        const uint32_t bbase = abase + CHUNK_BYTES;

        load_frags(abase, bbase, 0, 0);
#pragma unroll
        for (int kk = 0; kk < DK / 16; kk++) {
            const int cur = kk & 1;
            if (kk + 1 < DK / 16) load_frags(abase, bbase, kk + 1, cur ^ 1);
#pragma unroll
            for (int mi = 0; mi < 4; mi++)
#pragma unroll
                for (int ni = 0; ni < 8; ni++) {
                    asm volatile(
                        "mma.sync.aligned.m16n8k16.row.col.f32.bf16.bf16.f32 "
                        "{%0,%1,%2,%3}, {%4,%5,%6,%7}, {%8,%9}, {%0,%1,%2,%3};"
                        : "+f"(acc[mi][ni][0]), "+f"(acc[mi][ni][1]),
                          "+f"(acc[mi][ni][2]), "+f"(acc[mi][ni][3])
                        : "r"(afr[cur][mi][0]), "r"(afr[cur][mi][1]),
                          "r"(afr[cur][mi][2]), "r"(afr[cur][mi][3]),
                          "r"(bfr[cur][ni][0]), "r"(bfr[cur][ni][1]));
                }
        }

        if ((f & (NCHUNKS - 1)) == NCHUNKS - 1)
            tile_epilogue(blockIdx.x * TILES_PER_CTA + (f >> 2));
    }
}

// -------------------------------------------------------------------------
__device__ inline void lse_comb2(float& m, float& s, float m2, float s2)
{
    float M = fmaxf(m, m2);
    s = s * exp2f(m - M) + s2 * exp2f(m2 - M);
    m = M;
}

// Per-row combine (base-2), vectorized
__global__ void __launch_bounds__(128)
row_reduce_kernel(const float* __restrict__ online,
                  const float* __restrict__ mom,
                  const float* __restrict__ temp)
{
    const int row = blockIdx.x;
    const int tid = threadIdx.x;
    __shared__ float sm[128], ss[128], sp[128];

    float4 m4 = reinterpret_cast<const float4*>(g_pm + (size_t)row * NPART)[tid];
    float4 s4 = reinterpret_cast<const float4*>(g_ps + (size_t)row * NPART)[tid];
    float m = m4.x, s = s4.x;
    lse_comb2(m, s, m4.y, s4.y);
    lse_comb2(m, s, m4.z, s4.z);
    lse_comb2(m, s, m4.w, s4.w);

    float2 o  = reinterpret_cast<const float2*>(online + (size_t)row * DDIM)[tid];
    float2 mo = reinterpret_cast<const float2*>(mom    + (size_t)row * DDIM)[tid];
    float pv = o.x * mo.x + o.y * mo.y;

    sm[tid] = m; ss[tid] = s; sp[tid] = pv;
    __syncthreads();
    for (int o2 = 64; o2 > 0; o2 >>= 1) {
        if (tid < o2) {
            float mm = sm[tid], sv = ss[tid];
            lse_comb2(mm, sv, sm[tid + o2], ss[tid + o2]);
            sm[tid] = mm; ss[tid] = sv;
            sp[tid] += sp[tid + o2];
        }
        __syncthreads();
    }
    if (tid == 0) {
        float scale2 = (1.0f / temp[0]) * LOG2E;
        float pos2 = sp[0] * scale2;
        float M = fmaxf(sm[0], pos2);
        float S = ss[0] * exp2f(sm[0] - M) + exp2f(pos2 - M);
        g_loss[row] = LN2 * (M + log2f(S) - pos2);
    }
}

__global__ void __launch_bounds__(256)
final_mean_kernel(float* __restrict__ out)
{
    const int tid = threadIdx.x;
    __shared__ float sb[256];
    sb[tid] = g_loss[tid] + g_loss[tid + 256] + g_loss[tid + 512] + g_loss[tid + 768];
    __syncthreads();
    for (int o = 128; o > 0; o >>= 1) {
        if (tid < o) sb[tid] += sb[tid + o];
        __syncthreads();
    }
    if (tid == 0) {
        float l = sb[0] * (1.0f / (float)NROWS);
        out[0] = 0.7f * l + 0.3f * l;
    }
}

// -------------------------------------------------------------------------
extern "C" void kernel_launch(void* const* d_in, const int* in_sizes, int n_in,
                              void* d_out, int out_size)
{
    const float* online = (const float*)d_in[0];   // [1024, 256]
    const float* mom    = (const float*)d_in[1];   // [1024, 256]
    const float* queue  = (const float*)d_in[2];   // [256, 65536]
    const float* temp   = (const float*)d_in[3];   // [1]
    float* out = (float*)d_out;

    cudaFuncSetAttribute(gemm_lse_kernel,
                         cudaFuncAttributeMaxDynamicSharedMemorySize, SM_TOTAL);

    conv_a_kernel<<<128, 256>>>(online);
    {
        dim3 g(KCOLS / 64, DDIM / 64);             // (1024, 4)
        transpose_q_kernel<<<g, 256>>>(queue);
    }
    {
        dim3 g(NCOLBLK / TILES_PER_CTA, NROWS / BM);   // (256, 8)
        gemm_lse_kernel<<<g, THREADS, SM_TOTAL>>>(temp);
    }
    row_reduce_kernel<<<NROWS, 128>>>(online, mom, temp);
    final_mean_kernel<<<1, 256>>>(out);
}